// round 16
// baseline (speedup 1.0000x reference)
#include <cuda_runtime.h>
#include <cuda_bf16.h>

// Inputs (metadata order):
// 0: pred float32 [2M]  1: constr_idx int32 [20M]  2: var_idx int32 [20M]
// 3: coeff float32 [20M]  4: constr_rhs float32 [1M]  5: constr_sense int32 [1M]
// Output: scalar float (mean violation)
//
// Work-per-thread series (scatter, one-shot): 8 -> ~152.5, 4 -> 150.5,
// 2 -> ~149.5. This round: 1 nnz/thread (78125 blocks).

#define MAX_CONSTRS 1000000

__device__ float g_ax[MAX_CONSTRS];

// ---------------------------------------------------------------------------
__device__ __forceinline__ float fast_sigmoid(float x) {
    float t;
    asm("tanh.approx.f32 %0, %1;" : "=f"(t) : "f"(0.5f * x));
    return fmaf(0.5f, t, 0.5f);
}

// scatter: ax[cidx[k]] += coeff[k] * sigmoid(pred[vidx[k]]), 1 nnz/thread,
// one-shot. Maximum fresh-block injection; identical sector traffic.
__global__ void __launch_bounds__(256) scatter_kernel(
        const float* __restrict__ pred,
        const int*   __restrict__ cidx,
        const int*   __restrict__ vidx,
        const float* __restrict__ coeff,
        float* __restrict__ out,
        int n) {
    int i = blockIdx.x * blockDim.x + threadIdx.x;
    if (i == 0) *out = 0.0f;
    if (i >= n) return;

    int   c = __ldcs(&cidx[i]);
    int   v = __ldcs(&vidx[i]);
    float a = __ldcs(&coeff[i]);

    float p = __ldcg(&pred[v]);
    float g = fast_sigmoid(p);

    atomicAdd(&g_ax[c], a * g);
}

// ---------------------------------------------------------------------------
// reduce: violations + mean, 1 float4/thread, 977 blocks (measured best).
// ---------------------------------------------------------------------------
__device__ __forceinline__ float viol(float diff, int sn) {
    float v1 = fmaxf(diff, 0.0f);
    float v2 = fmaxf(-diff, 0.0f);
    float v3 = fabsf(diff);
    return (sn == 1) ? v1 : (sn == 2) ? v2 : (sn == 3) ? v3 : 0.0f;
}

__global__ void __launch_bounds__(256) reduce_kernel(
        const float4* __restrict__ rhs4,
        const int4*   __restrict__ sense4,
        float* __restrict__ out,
        int n4, float inv_n) {
    float s = 0.0f;
    const float4* ax4 = reinterpret_cast<const float4*>(g_ax);
    int i = blockIdx.x * blockDim.x + threadIdx.x;
    if (i < n4) {
        float4 ax = __ldcg(&ax4[i]);
        float4 rh = rhs4[i];
        int4   sn = sense4[i];
        s += viol(ax.x - rh.x, sn.x);
        s += viol(ax.y - rh.y, sn.y);
        s += viol(ax.z - rh.z, sn.z);
        s += viol(ax.w - rh.w, sn.w);
    }
    #pragma unroll
    for (int off = 16; off > 0; off >>= 1)
        s += __shfl_down_sync(0xFFFFFFFFu, s, off);

    __shared__ float warp_sums[8];
    int lane = threadIdx.x & 31;
    int wid  = threadIdx.x >> 5;
    if (lane == 0) warp_sums[wid] = s;
    __syncthreads();
    if (wid == 0) {
        float t = (lane < 8) ? warp_sums[lane] : 0.0f;
        #pragma unroll
        for (int off = 4; off > 0; off >>= 1)
            t += __shfl_down_sync(0xFFFFFFFFu, t, off);
        if (lane == 0) atomicAdd(out, t * inv_n);
    }
}

// ---------------------------------------------------------------------------
extern "C" void kernel_launch(void* const* d_in, const int* in_sizes, int n_in,
                              void* d_out, int out_size) {
    const float* pred   = (const float*)d_in[0];
    const int*   cidx   = (const int*)  d_in[1];
    const int*   vidx   = (const int*)  d_in[2];
    const float* coeff  = (const float*)d_in[3];
    const float* rhs    = (const float*)d_in[4];
    const int*   sense  = (const int*)  d_in[5];

    int nnz       = in_sizes[1];
    int n_constrs = in_sizes[4];

    float* out = (float*)d_out;

    // 1) zero ax via memset node
    {
        void* ax_ptr = nullptr;
        cudaGetSymbolAddress(&ax_ptr, g_ax);
        cudaMemsetAsync(ax_ptr, 0, (size_t)n_constrs * sizeof(float));
    }

    // 2) one-shot scatter (1 nnz/thread); also zeroes *out
    {
        int threads = 256;
        int blocks = (nnz + threads - 1) / threads;   // 78125
        scatter_kernel<<<blocks, threads>>>(pred, cidx, vidx, coeff, out, nnz);
    }

    // 3) violations + mean (1 float4/thread, 977 blocks)
    {
        int n4 = n_constrs / 4;                 // 250,000
        int threads = 256;
        int blocks = (n4 + threads - 1) / threads;   // 977
        reduce_kernel<<<blocks, threads>>>(
            reinterpret_cast<const float4*>(rhs),
            reinterpret_cast<const int4*>(sense),
            out, n4, 1.0f / (float)n_constrs);
    }
}

// round 17
// speedup vs baseline: 1.0464x; 1.0464x over previous
#include <cuda_runtime.h>
#include <cuda_bf16.h>

// Inputs (metadata order):
// 0: pred float32 [2M]  1: constr_idx int32 [20M]  2: var_idx int32 [20M]
// 3: coeff float32 [20M]  4: constr_rhs float32 [1M]  5: constr_sense int32 [1M]
// Output: scalar float (mean violation)
//
// FINAL (converged): each component at its measured-best configuration.
//   1) memset node zeroes g_ax                        (~1.5 us)
//   2) one-shot scatter, 2 nnz/thread, 39063 blocks   (~149.5 us, 93% LTS roofline)
//      - sigmoid fused in via tanh.approx (hides under LTS bound)
//      - .cs streaming loads, .cg L2-only gathers, no-return REDG atomics
//   3) reduce, 1 float4/thread, 977 blocks            (~7.8 us, DRAM-latency floor)
// Work-per-thread curve (measured): 8->152.5, 4->150.5, 2->149.5, 1->156.5.

#define MAX_CONSTRS 1000000

__device__ float g_ax[MAX_CONSTRS];

// ---------------------------------------------------------------------------
__device__ __forceinline__ float fast_sigmoid(float x) {
    float t;
    asm("tanh.approx.f32 %0, %1;" : "=f"(t) : "f"(0.5f * x));
    return fmaf(0.5f, t, 0.5f);
}

// scatter: ax[cidx[k]] += coeff[k] * sigmoid(pred[vidx[k]]), 2 nnz/thread.
__global__ void __launch_bounds__(256) scatter_kernel(
        const float*  __restrict__ pred,
        const int2*   __restrict__ cidx2,
        const int2*   __restrict__ vidx2,
        const float2* __restrict__ coeff2,
        float* __restrict__ out,
        int nthreads) {
    int i = blockIdx.x * blockDim.x + threadIdx.x;
    if (i == 0) *out = 0.0f;
    if (i >= nthreads) return;

    int2   c = __ldcs(&cidx2[i]);
    int2   v = __ldcs(&vidx2[i]);
    float2 a = __ldcs(&coeff2[i]);

    float p0 = __ldcg(&pred[v.x]);
    float p1 = __ldcg(&pred[v.y]);

    float g0 = fast_sigmoid(p0);
    float g1 = fast_sigmoid(p1);

    atomicAdd(&g_ax[c.x], a.x * g0);
    atomicAdd(&g_ax[c.y], a.y * g1);
}

// ---------------------------------------------------------------------------
// reduce: violations + mean, 1 float4/thread, 977 blocks.
// ---------------------------------------------------------------------------
__device__ __forceinline__ float viol(float diff, int sn) {
    float v1 = fmaxf(diff, 0.0f);
    float v2 = fmaxf(-diff, 0.0f);
    float v3 = fabsf(diff);
    return (sn == 1) ? v1 : (sn == 2) ? v2 : (sn == 3) ? v3 : 0.0f;
}

__global__ void __launch_bounds__(256) reduce_kernel(
        const float4* __restrict__ rhs4,
        const int4*   __restrict__ sense4,
        float* __restrict__ out,
        int n4, float inv_n) {
    float s = 0.0f;
    const float4* ax4 = reinterpret_cast<const float4*>(g_ax);
    int i = blockIdx.x * blockDim.x + threadIdx.x;
    if (i < n4) {
        float4 ax = __ldcg(&ax4[i]);
        float4 rh = rhs4[i];
        int4   sn = sense4[i];
        s += viol(ax.x - rh.x, sn.x);
        s += viol(ax.y - rh.y, sn.y);
        s += viol(ax.z - rh.z, sn.z);
        s += viol(ax.w - rh.w, sn.w);
    }
    #pragma unroll
    for (int off = 16; off > 0; off >>= 1)
        s += __shfl_down_sync(0xFFFFFFFFu, s, off);

    __shared__ float warp_sums[8];
    int lane = threadIdx.x & 31;
    int wid  = threadIdx.x >> 5;
    if (lane == 0) warp_sums[wid] = s;
    __syncthreads();
    if (wid == 0) {
        float t = (lane < 8) ? warp_sums[lane] : 0.0f;
        #pragma unroll
        for (int off = 4; off > 0; off >>= 1)
            t += __shfl_down_sync(0xFFFFFFFFu, t, off);
        if (lane == 0) atomicAdd(out, t * inv_n);
    }
}

// ---------------------------------------------------------------------------
extern "C" void kernel_launch(void* const* d_in, const int* in_sizes, int n_in,
                              void* d_out, int out_size) {
    const float* pred   = (const float*)d_in[0];
    const int*   cidx   = (const int*)  d_in[1];
    const int*   vidx   = (const int*)  d_in[2];
    const float* coeff  = (const float*)d_in[3];
    const float* rhs    = (const float*)d_in[4];
    const int*   sense  = (const int*)  d_in[5];

    int nnz       = in_sizes[1];
    int n_constrs = in_sizes[4];

    float* out = (float*)d_out;

    // 1) zero ax via memset node
    {
        void* ax_ptr = nullptr;
        cudaGetSymbolAddress(&ax_ptr, g_ax);
        cudaMemsetAsync(ax_ptr, 0, (size_t)n_constrs * sizeof(float));
    }

    // 2) one-shot scatter (2 nnz/thread); also zeroes *out
    {
        int nthreads = nnz / 2;   // 10,000,000
        int threads = 256;
        int blocks = (nthreads + threads - 1) / threads;   // 39063
        scatter_kernel<<<blocks, threads>>>(
            pred,
            reinterpret_cast<const int2*>(cidx),
            reinterpret_cast<const int2*>(vidx),
            reinterpret_cast<const float2*>(coeff),
            out, nthreads);
    }

    // 3) violations + mean (1 float4/thread, 977 blocks)
    {
        int n4 = n_constrs / 4;                 // 250,000
        int threads = 256;
        int blocks = (n4 + threads - 1) / threads;   // 977
        reduce_kernel<<<blocks, threads>>>(
            reinterpret_cast<const float4*>(rhs),
            reinterpret_cast<const int4*>(sense),
            out, n4, 1.0f / (float)n_constrs);
    }
}